// round 8
// baseline (speedup 1.0000x reference)
#include <cuda_runtime.h>
#include <cuda_fp16.h>
#include <cstdint>

// Problem constants
#define BB 64
#define SS 1024
#define CC 512
#define SC (SS*CC)
#define NN (BB*CC)          // 32768 = total N of the big GEMM
#define EPS 1e-5f
#define RED_CHUNKS 64
#define BK 32               // k-tile (halves)
#define NT (SS / BK)        // 32 k-tiles

// Scratch (device globals; 16B-aligned for cp.async / uint4)
__device__ float2 g_partials[BB * RED_CHUNKS];
__device__ float2 g_stats[BB];
// K-panel layouts: [(kt*ROWS + row)*32 + ks], fp16
__device__ __align__(16) __half g_Hp[(size_t)NN * SS];     // B panels (64MB)
__device__ __align__(16) __half g_Wh[(size_t)SS * SS];     // A panels (2MB)

// ---------------------------------------------------------------------------
// helpers
// ---------------------------------------------------------------------------
__device__ __forceinline__ uint32_t smem_to_u32(const void* p) {
    uint32_t a;
    asm("{ .reg .u64 t; cvta.to.shared.u64 t, %1; cvt.u32.u64 %0, t; }" : "=r"(a) : "l"(p));
    return a;
}
__device__ __forceinline__ void ldmatrix_x4(uint32_t& r0, uint32_t& r1,
                                            uint32_t& r2, uint32_t& r3, uint32_t addr) {
    asm volatile("ldmatrix.sync.aligned.m8n8.x4.shared.b16 {%0,%1,%2,%3}, [%4];"
                 : "=r"(r0), "=r"(r1), "=r"(r2), "=r"(r3) : "r"(addr));
}
__device__ __forceinline__ void mma_f16(float* d, const uint32_t* a,
                                        uint32_t b0, uint32_t b1) {
    asm volatile(
        "mma.sync.aligned.m16n8k16.row.col.f32.f16.f16.f32 "
        "{%0,%1,%2,%3}, {%4,%5,%6,%7}, {%8,%9}, {%0,%1,%2,%3};"
        : "+f"(d[0]), "+f"(d[1]), "+f"(d[2]), "+f"(d[3])
        : "r"(a[0]), "r"(a[1]), "r"(a[2]), "r"(a[3]), "r"(b0), "r"(b1));
}
__device__ __forceinline__ void cp16(uint32_t dst, const void* src) {
    asm volatile("cp.async.cg.shared.global [%0], [%1], 16;" :: "r"(dst), "l"(src));
}
#define CP_COMMIT() asm volatile("cp.async.commit_group;" ::: "memory")
#define CP_WAIT2()  asm volatile("cp.async.wait_group 2;" ::: "memory")

__device__ __forceinline__ uint32_t pack2(float a, float b) {
    __half2 h = __floats2half2_rn(a, b);
    return *reinterpret_cast<uint32_t*>(&h);
}

// ---------------------------------------------------------------------------
// Kernel 1: per-batch partial sums (sum, sumsq). Deterministic fixed tree.
// ---------------------------------------------------------------------------
__global__ void reduce_kernel(const float* __restrict__ x) {
    const int b     = blockIdx.x / RED_CHUNKS;
    const int chunk = blockIdx.x % RED_CHUNKS;
    const int n4    = SC / RED_CHUNKS / 4;
    const float4* px = reinterpret_cast<const float4*>(x + (size_t)b * SC) + (size_t)chunk * n4;

    float s = 0.f, sq = 0.f;
    for (int i = threadIdx.x; i < n4; i += blockDim.x) {
        float4 v = px[i];
        s  += v.x + v.y + v.z + v.w;
        sq += v.x*v.x + v.y*v.y + v.z*v.z + v.w*v.w;
    }
    __shared__ float ss[8], ssq[8];
    #pragma unroll
    for (int o = 16; o > 0; o >>= 1) {
        s  += __shfl_down_sync(0xffffffff, s,  o);
        sq += __shfl_down_sync(0xffffffff, sq, o);
    }
    if ((threadIdx.x & 31) == 0) { ss[threadIdx.x >> 5] = s; ssq[threadIdx.x >> 5] = sq; }
    __syncthreads();
    if (threadIdx.x == 0) {
        float ts = 0.f, tsq = 0.f;
        #pragma unroll
        for (int w = 0; w < 8; w++) { ts += ss[w]; tsq += ssq[w]; }
        g_partials[blockIdx.x] = make_float2(ts, tsq);
    }
}

__global__ void stats_kernel() {
    int b = threadIdx.x;
    if (b < BB) {
        float s = 0.f, sq = 0.f;
        #pragma unroll 8
        for (int i = 0; i < RED_CHUNKS; i++) {
            float2 p = g_partials[b * RED_CHUNKS + i];
            s += p.x; sq += p.y;
        }
        float mu  = s / (float)SC;
        float var = fmaxf(sq / (float)SC - mu * mu, 0.f);
        g_stats[b] = make_float2(mu, rsqrtf(var + EPS));
    }
}

// ---------------------------------------------------------------------------
// Kernel 2b: convert W (fp32 [m][s]) -> g_Wh fp16 K-panels [(kt*1024+m)*32+ks].
// ---------------------------------------------------------------------------
__global__ void convert_w_kernel(const float* __restrict__ W) {
    __shared__ float tile[32][33];
    const int m0 = blockIdx.x * 32;
    const int s0 = blockIdx.y * 32;
    #pragma unroll
    for (int i = 0; i < 4; i++)
        tile[threadIdx.y + i * 8][threadIdx.x] =
            W[(size_t)(m0 + threadIdx.y + i * 8) * SS + s0 + threadIdx.x];
    __syncthreads();
    const int idx = threadIdx.y * 32 + threadIdx.x;
    if (idx < 128) {
        const int m     = idx >> 2;
        const int chunk = idx & 3;
        const int kt    = s0 >> 5;
        uint4 pk;
        pk.x = pack2(tile[m][chunk*8+0], tile[m][chunk*8+1]);
        pk.y = pack2(tile[m][chunk*8+2], tile[m][chunk*8+3]);
        pk.z = pack2(tile[m][chunk*8+4], tile[m][chunk*8+5]);
        pk.w = pack2(tile[m][chunk*8+6], tile[m][chunk*8+7]);
        *reinterpret_cast<uint4*>(g_Wh + ((size_t)kt * SS + m0 + m) * 32 + chunk * 8) = pk;
    }
}

// ---------------------------------------------------------------------------
// Kernel 3: fused LayerNorm + transpose -> g_Hp K-panels [(kt*NN + n)*32 + ks].
// ---------------------------------------------------------------------------
__global__ void normalize_t_kernel(const float* __restrict__ x,
                                   const float* __restrict__ lnw,
                                   const float* __restrict__ lnb) {
    __shared__ float tile[32][33];     // [s_local][c_local]
    const int b  = blockIdx.z;
    const int s0 = blockIdx.x * 32;
    const int c0 = blockIdx.y * 32;
    const float2 st = g_stats[b];

    #pragma unroll
    for (int i = 0; i < 4; i++) {
        int s = s0 + threadIdx.y + i * 8;
        int c = c0 + threadIdx.x;
        float v  = x  [(size_t)b * SC + (size_t)s * CC + c];
        float w  = lnw[(size_t)s * CC + c];
        float bb = lnb[(size_t)s * CC + c];
        tile[threadIdx.y + i * 8][threadIdx.x] = (v - st.x) * st.y * w + bb;
    }
    __syncthreads();
    const int idx = threadIdx.y * 32 + threadIdx.x;
    if (idx < 128) {
        const int c     = idx >> 2;
        const int chunk = idx & 3;
        const int kt    = s0 >> 5;
        const int n     = b * CC + c0 + c;
        uint4 pk;
        pk.x = pack2(tile[chunk*8+0][c], tile[chunk*8+1][c]);
        pk.y = pack2(tile[chunk*8+2][c], tile[chunk*8+3][c]);
        pk.z = pack2(tile[chunk*8+4][c], tile[chunk*8+5][c]);
        pk.w = pack2(tile[chunk*8+6][c], tile[chunk*8+7][c]);
        *reinterpret_cast<uint4*>(g_Hp + ((size_t)kt * NN + n) * 32 + chunk * 8) = pk;
    }
}

// ---------------------------------------------------------------------------
// Kernel 4: fp16 GEMM, fp32 acc. D[1024, 32768] = Wh x Hp^T, K=1024.
// CTA 128(M) x 256(N) x 32(K). 256 threads, 8 warps (2M x 4N), warp 64x64
// (minimal fragment redundancy: 64KB LDSM/tile). 4-stage cp.async pipeline.
// smem rows 80B (conflict-free ldmatrix). Epilogue: out = x + relu(D + bias).
// ---------------------------------------------------------------------------
#define BM 128
#define BN 256
#define AST (BM * 80)              // 10240 B per A stage
#define BST (BN * 80)              // 20480 B per B stage
#define NSTG 4
#define OFF_BS (NSTG * AST)        // B stages base
#define GSMEM (NSTG * (AST + BST)) // 122880 B

__global__ __launch_bounds__(256, 1)
void gemm_f16(const float* __restrict__ linb,
              const float* __restrict__ x, float* __restrict__ out)
{
    extern __shared__ char smem[];
    const uint32_t sb = smem_to_u32(smem);

    const int tid  = threadIdx.x;
    const int lane = tid & 31;
    const int wid  = tid >> 5;
    const int wm   = (wid >> 2) * 64;       // 0 / 64
    const int wn   = (wid & 3) * 64;        // 0..192
    const int m0   = blockIdx.x * BM;
    const int n0   = blockIdx.y * BN;

    float acc[4][8][4];
    #pragma unroll
    for (int i = 0; i < 4; i++)
        #pragma unroll
        for (int j = 0; j < 8; j++)
            #pragma unroll
            for (int k = 0; k < 4; k++) acc[i][j][k] = 0.f;

    // cp.async chunk mapping (16B chunks from contiguous panels, 256 threads)
    const int aRow = tid >> 2;           // A rows 0..63 (+64): 2 chunks/thread
    const int aPrt = tid & 3;
    const int bRow = tid >> 2;           // B rows: 4 chunks/thread
    const int bPrt = tid & 3;

    const __half* Apan = g_Wh + ((size_t)m0) * 32;  // + t*SS*32 per tile
    const __half* Bpan = g_Hp + ((size_t)n0) * 32;  // + t*NN*32 per tile

    #define ISSUE(t, st)                                                          \
        do {                                                                      \
            const __half* asrc = Apan + (size_t)(t) * SS * 32;                    \
            const __half* bsrc = Bpan + (size_t)(t) * NN * 32;                    \
            _Pragma("unroll")                                                     \
            for (int j = 0; j < 2; j++) {                                         \
                int m = aRow + j * 64;                                            \
                cp16(sb + (st) * AST + m * 80 + aPrt * 16,                        \
                     asrc + (size_t)m * 32 + aPrt * 8);                           \
            }                                                                     \
            _Pragma("unroll")                                                     \
            for (int j = 0; j < 4; j++) {                                         \
                int n = bRow + j * 64;                                            \
                cp16(sb + OFF_BS + (st) * BST + n * 80 + bPrt * 16,               \
                     bsrc + (size_t)n * 32 + bPrt * 8);                           \
            }                                                                     \
        } while (0)

    // ldmatrix base addresses
    const int l15 = lane & 15;
    const int lhi = lane >> 4;
    const uint32_t aLd = sb + (wm + l15) * 80 + lhi * 16;
    const uint32_t bLd = sb + OFF_BS + (wn + l15) * 80 + lhi * 16;

    // prologue: stages 0,1,2
    ISSUE(0, 0); CP_COMMIT();
    ISSUE(1, 1); CP_COMMIT();
    ISSUE(2, 2); CP_COMMIT();

    for (int t = 0; t < NT; t++) {
        const int st = t & (NSTG - 1);
        CP_WAIT2();                 // group t complete (t+1, t+2 may pend)
        __syncthreads();            // all warps done with tile t-1's stage
        if (t + 3 < NT) ISSUE(t + 3, (t + 3) & (NSTG - 1));
        CP_COMMIT();

        #pragma unroll
        for (int ks = 0; ks < 2; ks++) {
            uint32_t a[4][4], bm_[4][4];
            #pragma unroll
            for (int i = 0; i < 4; i++)
                ldmatrix_x4(a[i][0], a[i][1], a[i][2], a[i][3],
                            aLd + st * AST + i * 16 * 80 + ks * 32);
            #pragma unroll
            for (int j = 0; j < 4; j++)
                ldmatrix_x4(bm_[j][0], bm_[j][1], bm_[j][2], bm_[j][3],
                            bLd + st * BST + j * 16 * 80 + ks * 32);
            #pragma unroll
            for (int i = 0; i < 4; i++)
                #pragma unroll
                for (int j = 0; j < 4; j++) {
                    mma_f16(acc[i][2*j    ], a[i], bm_[j][0], bm_[j][2]);
                    mma_f16(acc[i][2*j + 1], a[i], bm_[j][1], bm_[j][3]);
                }
        }
    }

    // Epilogue: n -> (batch, channel); whole CTA sits in one batch.
    const int bidx = n0 >> 9;
    const int c0   = n0 & 511;
    const float* xb = x   + (size_t)bidx * SC;
    float*       ob = out + (size_t)bidx * SC;

    #pragma unroll
    for (int i = 0; i < 4; i++) {
        const int t0 = m0 + wm + i * 16 + (lane >> 2);
        const float bias0 = __ldg(linb + t0);
        const float bias1 = __ldg(linb + t0 + 8);
        #pragma unroll
        for (int j = 0; j < 8; j++) {
            const int c = c0 + wn + j * 8 + (lane & 3) * 2;
            float2 xv0 = *reinterpret_cast<const float2*>(xb + (size_t)t0 * CC + c);
            float2 o0;
            o0.x = xv0.x + fmaxf(acc[i][j][0] + bias0, 0.f);
            o0.y = xv0.y + fmaxf(acc[i][j][1] + bias0, 0.f);
            *reinterpret_cast<float2*>(ob + (size_t)t0 * CC + c) = o0;

            float2 xv1 = *reinterpret_cast<const float2*>(xb + (size_t)(t0 + 8) * CC + c);
            float2 o1;
            o1.x = xv1.x + fmaxf(acc[i][j][2] + bias1, 0.f);
            o1.y = xv1.y + fmaxf(acc[i][j][3] + bias1, 0.f);
            *reinterpret_cast<float2*>(ob + (size_t)(t0 + 8) * CC + c) = o1;
        }
    }
}

// ---------------------------------------------------------------------------
// Launch
// ---------------------------------------------------------------------------
extern "C" void kernel_launch(void* const* d_in, const int* in_sizes, int n_in,
                              void* d_out, int out_size) {
    const float* x     = (const float*)d_in[0];
    const float* ln_w  = (const float*)d_in[1];
    const float* ln_b  = (const float*)d_in[2];
    const float* lin_w = (const float*)d_in[3];
    const float* lin_b = (const float*)d_in[4];
    float* out = (float*)d_out;

    cudaFuncSetAttribute(gemm_f16, cudaFuncAttributeMaxDynamicSharedMemorySize, GSMEM);

    reduce_kernel<<<BB * RED_CHUNKS, 256>>>(x);
    stats_kernel<<<1, 64>>>();
    convert_w_kernel<<<dim3(32, 32), dim3(32, 8)>>>(lin_w);
    normalize_t_kernel<<<dim3(SS / 32, CC / 32, BB), dim3(32, 8)>>>(x, ln_w, ln_b);

    // M=1024 (8 x 128), N=32768 (128 x 256)
    gemm_f16<<<dim3(8, 128), 256, GSMEM>>>(lin_b, x, out);
}